// round 1
// baseline (speedup 1.0000x reference)
#include <cuda_runtime.h>
#include <cuda_bf16.h>
#include <cstdint>

// ---------------- problem constants ----------------
#define N_NODES 100000
#define N_EDGES 600000
#define HID 128

// ---------------- scratch (device globals; no allocation allowed) ----------
__device__ float g_h   [(size_t)N_NODES * HID];
__device__ float g_agg [(size_t)N_NODES * HID];
__device__ float g_hid [(size_t)N_NODES * HID];
__device__ float g_ehid[(size_t)N_EDGES * HID];

// ---------------- generic SGEMM: C[M,N] = A[M,K] @ W[K,N] (+bias)(+relu) ----
// BM=128, BN=128, BK=16, thread tile 8x8, 256 threads.
// Requires K % 16 == 0 (true for 64/128/288), float4-aligned rows.
#define BM 128
#define BN 128
#define BK 16

template<bool RELU>
__global__ __launch_bounds__(256)
void sgemm_kernel(const float* __restrict__ A, int lda,
                  const float* __restrict__ W, int ldw,
                  const float* __restrict__ bias,
                  float* __restrict__ C, int ldc,
                  int M, int N, int K)
{
    __shared__ float As[BK][BM];
    __shared__ float Ws[BK][BN];

    const int tid = threadIdx.x;
    const int m0 = blockIdx.y * BM;
    const int n0 = blockIdx.x * BN;
    const int tx = tid & 15;   // 16 col groups
    const int ty = tid >> 4;   // 16 row groups

    float acc[8][8];
    #pragma unroll
    for (int i = 0; i < 8; i++)
        #pragma unroll
        for (int j = 0; j < 8; j++) acc[i][j] = 0.f;

    for (int k0 = 0; k0 < K; k0 += BK) {
        // --- load A tile: 128 rows x 16 k, float4 along k, store transposed
        #pragma unroll
        for (int p = 0; p < 2; p++) {
            int idx = tid + p * 256;         // 0..511
            int m   = idx >> 2;              // 0..127
            int k4  = (idx & 3) << 2;        // 0,4,8,12
            float4 v = make_float4(0.f, 0.f, 0.f, 0.f);
            int gm = m0 + m;
            if (gm < M)
                v = *reinterpret_cast<const float4*>(A + (size_t)gm * lda + k0 + k4);
            As[k4 + 0][m] = v.x;
            As[k4 + 1][m] = v.y;
            As[k4 + 2][m] = v.z;
            As[k4 + 3][m] = v.w;
        }
        // --- load W tile: 16 k x 128 n, float4 along n
        #pragma unroll
        for (int p = 0; p < 2; p++) {
            int idx = tid + p * 256;         // 0..511
            int k   = idx >> 5;              // 0..15
            int n4  = (idx & 31) << 2;       // 0..124
            float4 v = make_float4(0.f, 0.f, 0.f, 0.f);
            int gn = n0 + n4;
            if (gn < N)
                v = *reinterpret_cast<const float4*>(W + (size_t)(k0 + k) * ldw + gn);
            *reinterpret_cast<float4*>(&Ws[k][n4]) = v;
        }
        __syncthreads();

        #pragma unroll
        for (int kk = 0; kk < BK; kk++) {
            float a[8], b[8];
            *reinterpret_cast<float4*>(&a[0]) = *reinterpret_cast<float4*>(&As[kk][ty * 8]);
            *reinterpret_cast<float4*>(&a[4]) = *reinterpret_cast<float4*>(&As[kk][ty * 8 + 4]);
            *reinterpret_cast<float4*>(&b[0]) = *reinterpret_cast<float4*>(&Ws[kk][tx * 8]);
            *reinterpret_cast<float4*>(&b[4]) = *reinterpret_cast<float4*>(&Ws[kk][tx * 8 + 4]);
            #pragma unroll
            for (int i = 0; i < 8; i++)
                #pragma unroll
                for (int j = 0; j < 8; j++)
                    acc[i][j] = fmaf(a[i], b[j], acc[i][j]);
        }
        __syncthreads();
    }

    // --- epilogue
    #pragma unroll
    for (int i = 0; i < 8; i++) {
        int gm = m0 + ty * 8 + i;
        if (gm >= M) continue;
        #pragma unroll
        for (int j = 0; j < 8; j++) {
            int gn = n0 + tx * 8 + j;
            if (gn >= N) continue;
            float v = acc[i][j];
            if (bias) v += bias[gn];
            if (RELU) v = fmaxf(v, 0.f);
            C[(size_t)gm * ldc + gn] = v;
        }
    }
}

// ---------------- copy kernel (agg := h, i.e. z starts at (1+eps)*h) -------
__global__ void copy_kernel(float* __restrict__ dst, const float* __restrict__ src, int n4)
{
    int i = blockIdx.x * blockDim.x + threadIdx.x;
    if (i < n4)
        reinterpret_cast<float4*>(dst)[i] = reinterpret_cast<const float4*>(src)[i];
}

// ---------------- fused edge-embedding + message + scatter-add -------------
// For each edge e: m = relu(h[src] + edge_attr[e] @ ew + eb); agg[dst] += m
// Block = 128 threads (one per HID dim); 32 edges per block.
// Each thread keeps its 32-element column of ew in registers.
__global__ __launch_bounds__(128)
void edge_scatter_kernel(const float* __restrict__ h,
                         const int* __restrict__ src,
                         const int* __restrict__ dst,
                         const float* __restrict__ ea,   // [E,32]
                         const float* __restrict__ ew,   // [32,128]
                         const float* __restrict__ eb,   // [128]
                         float* __restrict__ agg,
                         int E)
{
    __shared__ float ea_s[32 * 32];
    __shared__ int src_s[32];
    __shared__ int dst_s[32];

    const int d = threadIdx.x;          // 0..127
    float wcol[32];
    #pragma unroll
    for (int k = 0; k < 32; k++) wcol[k] = ew[k * HID + d];
    const float bd = eb[d];

    const int base = blockIdx.x * 32;
    const int ne = min(32, E - base);
    if (ne <= 0) return;

    for (int idx = threadIdx.x; idx < ne * 32; idx += 128)
        ea_s[idx] = ea[(size_t)base * 32 + idx];
    if (threadIdx.x < ne) {
        src_s[threadIdx.x] = src[base + threadIdx.x];
        dst_s[threadIdx.x] = dst[base + threadIdx.x];
    }
    __syncthreads();

    for (int e = 0; e < ne; e++) {
        const float* eav = &ea_s[e * 32];
        float v = bd;
        #pragma unroll
        for (int k = 0; k < 32; k++)
            v = fmaf(eav[k], wcol[k], v);           // e_emb[d]
        v += h[(size_t)src_s[e] * HID + d];         // + h[src][d]
        v = fmaxf(v, 0.f);                          // relu
        atomicAdd(&agg[(size_t)dst_s[e] * HID + d], v);
    }
}

// ---------------- fused classifier hidden layer ----------------------------
// hidden[e][d] = relu(P[src][d] + Q[dst][d] + ea[e] @ W1c[:,d] + b1[d])
__global__ __launch_bounds__(128)
void edge_hidden_kernel(const float* __restrict__ P,
                        const float* __restrict__ Q,
                        const int* __restrict__ src,
                        const int* __restrict__ dst,
                        const float* __restrict__ ea,    // [E,32]
                        const float* __restrict__ w1c,   // [32,128]
                        const float* __restrict__ b1,    // [128]
                        float* __restrict__ out,         // [E,128]
                        int E)
{
    __shared__ float ea_s[32 * 32];
    __shared__ int src_s[32];
    __shared__ int dst_s[32];

    const int d = threadIdx.x;
    float wcol[32];
    #pragma unroll
    for (int k = 0; k < 32; k++) wcol[k] = w1c[k * HID + d];
    const float bd = b1[d];

    const int base = blockIdx.x * 32;
    const int ne = min(32, E - base);
    if (ne <= 0) return;

    for (int idx = threadIdx.x; idx < ne * 32; idx += 128)
        ea_s[idx] = ea[(size_t)base * 32 + idx];
    if (threadIdx.x < ne) {
        src_s[threadIdx.x] = src[base + threadIdx.x];
        dst_s[threadIdx.x] = dst[base + threadIdx.x];
    }
    __syncthreads();

    for (int e = 0; e < ne; e++) {
        const float* eav = &ea_s[e * 32];
        float v = bd;
        #pragma unroll
        for (int k = 0; k < 32; k++)
            v = fmaf(eav[k], wcol[k], v);
        v += P[(size_t)src_s[e] * HID + d];
        v += Q[(size_t)dst_s[e] * HID + d];
        v = fmaxf(v, 0.f);
        out[(size_t)(base + e) * HID + d] = v;
    }
}

// ---------------- host orchestration ---------------------------------------
extern "C" void kernel_launch(void* const* d_in, const int* in_sizes, int n_in,
                              void* d_out, int out_size)
{
    const float* x      = (const float*)d_in[0];
    const int*   eidx   = (const int*)  d_in[1];
    const float* ea     = (const float*)d_in[2];
    const float* lin1_w = (const float*)d_in[3];
    const float* lin1_b = (const float*)d_in[4];
    const float* cls_w1 = (const float*)d_in[23];
    const float* cls_b1 = (const float*)d_in[24];
    const float* cls_w2 = (const float*)d_in[25];
    const float* cls_b2 = (const float*)d_in[26];

    const int NN = in_sizes[0] / 64;    // nodes (x is [N,64])
    const int E  = in_sizes[2] / 32;    // edges (edge_attr is [E,32])
    const int* src = eidx;
    const int* dst = eidx + E;

    float *h, *agg, *hid, *ehid;
    cudaGetSymbolAddress((void**)&h,    g_h);
    cudaGetSymbolAddress((void**)&agg,  g_agg);
    cudaGetSymbolAddress((void**)&hid,  g_hid);
    cudaGetSymbolAddress((void**)&ehid, g_ehid);

    auto gdim = [](int M, int N) {
        return dim3((unsigned)((N + BN - 1) / BN), (unsigned)((M + BM - 1) / BM));
    };
    const int eblocks = (E + 31) / 32;
    const int copy_n4 = (NN * HID) / 4;
    const int copy_blocks = (copy_n4 + 255) / 256;

    // h = x @ lin1_w + lin1_b
    sgemm_kernel<false><<<gdim(NN, HID), 256>>>(x, 64, lin1_w, HID, lin1_b,
                                                h, HID, NN, HID, 64);

    for (int c = 0; c < 3; c++) {
        const float* ew = (const float*)d_in[5 + 6 * c];
        const float* eb = (const float*)d_in[6 + 6 * c];
        const float* w1 = (const float*)d_in[7 + 6 * c];
        const float* b1 = (const float*)d_in[8 + 6 * c];
        const float* w2 = (const float*)d_in[9 + 6 * c];
        const float* b2 = (const float*)d_in[10 + 6 * c];

        // z := h (eps=0), then scatter-add messages into it
        copy_kernel<<<copy_blocks, 256>>>(agg, h, copy_n4);
        edge_scatter_kernel<<<eblocks, 128>>>(h, src, dst, ea, ew, eb, agg, E);
        // h = relu( relu(z@w1+b1) @ w2 + b2 )
        sgemm_kernel<true><<<gdim(NN, HID), 256>>>(agg, HID, w1, HID, b1,
                                                   hid, HID, NN, HID, HID);
        sgemm_kernel<true><<<gdim(NN, HID), 256>>>(hid, HID, w2, HID, b2,
                                                   h, HID, NN, HID, HID);
    }

    // Classifier: edge_feat @ W1 = h[src]@W1a + h[dst]@W1b + ea@W1c
    // P = h @ W1[0:128], Q = h @ W1[128:256]  (node-level, reuse hid/agg)
    sgemm_kernel<false><<<gdim(NN, HID), 256>>>(h, HID, cls_w1, HID, nullptr,
                                                hid, HID, NN, HID, HID);
    sgemm_kernel<false><<<gdim(NN, HID), 256>>>(h, HID, cls_w1 + 128 * HID, HID, nullptr,
                                                agg, HID, NN, HID, HID);
    // hidden = relu(P[src] + Q[dst] + ea@W1c + b1)
    edge_hidden_kernel<<<eblocks, 128>>>(hid, agg, src, dst, ea,
                                         cls_w1 + 256 * HID, cls_b1, ehid, E);
    // out = hidden @ cls_w2 + cls_b2
    sgemm_kernel<false><<<gdim(E, 24), 256>>>(ehid, HID, cls_w2, 24, cls_b2,
                                              (float*)d_out, 24, E, 24, HID);
}

// round 2
// speedup vs baseline: 1.3699x; 1.3699x over previous
#include <cuda_runtime.h>
#include <cuda_bf16.h>
#include <cstdint>

#define N_NODES 100000
#define N_EDGES 600000
#define HID 128
#define OUT 24

// ---------------- scratch ----------------
__device__ float g_h  [(size_t)N_NODES * HID];
__device__ float g_agg[(size_t)N_NODES * HID];
__device__ float g_hid[(size_t)N_NODES * HID];

// ---------------- packed f32x2 helpers ----------------
__device__ __forceinline__ unsigned long long pk2(float lo, float hi) {
    unsigned long long r;
    asm("mov.b64 %0, {%1, %2};" : "=l"(r) : "f"(lo), "f"(hi));
    return r;
}
__device__ __forceinline__ void fma2(unsigned long long& d,
                                     unsigned long long a, unsigned long long b) {
    asm("fma.rn.f32x2 %0, %1, %2, %0;" : "+l"(d) : "l"(a), "l"(b));
}
__device__ __forceinline__ float2 upk(unsigned long long v) {
    float2 f;
    asm("mov.b64 {%0, %1}, %2;" : "=f"(f.x), "=f"(f.y) : "l"(v));
    return f;
}

// ---------------- SGEMM: C[M,N]=A[M,K]@W[K,N](+bias)(+relu), N==128 -------
#define BM 128
#define BN 128
#define BK 16

template<bool RELU>
__global__ __launch_bounds__(256)
void sgemm_kernel(const float* __restrict__ A, int lda,
                  const float* __restrict__ W, int ldw,
                  const float* __restrict__ bias,
                  float* __restrict__ C, int ldc,
                  int M, int K)
{
    __shared__ float As[BK][BM];
    __shared__ float Ws[BK][BN];

    const int tid = threadIdx.x;
    const int m0 = blockIdx.y * BM;
    const int tx = tid & 15;
    const int ty = tid >> 4;

    unsigned long long acc2[8][4];
    #pragma unroll
    for (int i = 0; i < 8; i++)
        #pragma unroll
        for (int j = 0; j < 4; j++) acc2[i][j] = 0ull;

    for (int k0 = 0; k0 < K; k0 += BK) {
        #pragma unroll
        for (int p = 0; p < 2; p++) {
            int idx = tid + p * 256;
            int m   = idx >> 2;
            int k4  = (idx & 3) << 2;
            float4 v = make_float4(0.f, 0.f, 0.f, 0.f);
            int gm = m0 + m;
            if (gm < M)
                v = *reinterpret_cast<const float4*>(A + (size_t)gm * lda + k0 + k4);
            As[k4 + 0][m] = v.x;
            As[k4 + 1][m] = v.y;
            As[k4 + 2][m] = v.z;
            As[k4 + 3][m] = v.w;
        }
        #pragma unroll
        for (int p = 0; p < 2; p++) {
            int idx = tid + p * 256;
            int k   = idx >> 5;
            int n4  = (idx & 31) << 2;
            *reinterpret_cast<float4*>(&Ws[k][n4]) =
                *reinterpret_cast<const float4*>(W + (size_t)(k0 + k) * ldw + n4);
        }
        __syncthreads();

        #pragma unroll
        for (int kk = 0; kk < BK; kk++) {
            float a[8];
            *reinterpret_cast<float4*>(&a[0]) = *reinterpret_cast<float4*>(&As[kk][ty * 8]);
            *reinterpret_cast<float4*>(&a[4]) = *reinterpret_cast<float4*>(&As[kk][ty * 8 + 4]);
            unsigned long long b2[4];
            const unsigned long long* bp =
                reinterpret_cast<const unsigned long long*>(&Ws[kk][tx * 8]);
            #pragma unroll
            for (int j = 0; j < 4; j++) b2[j] = bp[j];
            #pragma unroll
            for (int i = 0; i < 8; i++) {
                unsigned long long a2 = pk2(a[i], a[i]);
                #pragma unroll
                for (int j = 0; j < 4; j++)
                    fma2(acc2[i][j], a2, b2[j]);
            }
        }
        __syncthreads();
    }

    const int gn = tx * 8;
    float4 bia0 = make_float4(0.f,0.f,0.f,0.f), bia1 = bia0;
    if (bias) {
        bia0 = *reinterpret_cast<const float4*>(bias + gn);
        bia1 = *reinterpret_cast<const float4*>(bias + gn + 4);
    }
    #pragma unroll
    for (int i = 0; i < 8; i++) {
        int gm = m0 + ty * 8 + i;
        if (gm >= M) continue;
        float2 p0 = upk(acc2[i][0]), p1 = upk(acc2[i][1]);
        float2 p2 = upk(acc2[i][2]), p3 = upk(acc2[i][3]);
        float4 v0 = make_float4(p0.x + bia0.x, p0.y + bia0.y, p1.x + bia0.z, p1.y + bia0.w);
        float4 v1 = make_float4(p2.x + bia1.x, p2.y + bia1.y, p3.x + bia1.z, p3.y + bia1.w);
        if (RELU) {
            v0.x = fmaxf(v0.x, 0.f); v0.y = fmaxf(v0.y, 0.f);
            v0.z = fmaxf(v0.z, 0.f); v0.w = fmaxf(v0.w, 0.f);
            v1.x = fmaxf(v1.x, 0.f); v1.y = fmaxf(v1.y, 0.f);
            v1.z = fmaxf(v1.z, 0.f); v1.w = fmaxf(v1.w, 0.f);
        }
        float* cp = C + (size_t)gm * ldc + gn;
        *reinterpret_cast<float4*>(cp)     = v0;
        *reinterpret_cast<float4*>(cp + 4) = v1;
    }
}

// ---------------- copy kernel ----------------
__global__ void copy_kernel(float* __restrict__ dst, const float* __restrict__ src, int n4)
{
    int i = blockIdx.x * blockDim.x + threadIdx.x;
    if (i < n4)
        reinterpret_cast<float4*>(dst)[i] = reinterpret_cast<const float4*>(src)[i];
}

// ---------------- fused edge-embedding + message + scatter-add -------------
__global__ __launch_bounds__(128)
void edge_scatter_kernel(const float* __restrict__ h,
                         const int* __restrict__ src,
                         const int* __restrict__ dst,
                         const float* __restrict__ ea,
                         const float* __restrict__ ew,
                         const float* __restrict__ eb,
                         float* __restrict__ agg,
                         int E)
{
    __shared__ float ea_s[32][32];
    __shared__ int src_s[32];
    __shared__ int dst_s[32];

    const int d = threadIdx.x;
    unsigned long long wcol2[16];
    #pragma unroll
    for (int t = 0; t < 16; t++)
        wcol2[t] = pk2(ew[(2 * t) * HID + d], ew[(2 * t + 1) * HID + d]);
    const float bd = eb[d];

    const int base = blockIdx.x * 32;
    const int ne = min(32, E - base);
    if (ne <= 0) return;

    for (int idx = threadIdx.x; idx < ne * 32; idx += 128)
        ea_s[idx >> 5][idx & 31] = ea[(size_t)base * 32 + idx];
    if (threadIdx.x < ne) {
        src_s[threadIdx.x] = src[base + threadIdx.x];
        dst_s[threadIdx.x] = dst[base + threadIdx.x];
    }
    __syncthreads();

    // software-pipelined gather of h[src]
    float hs = h[(size_t)src_s[0] * HID + d];
    for (int e = 0; e < ne; e++) {
        float hs_next = 0.f;
        if (e + 1 < ne) hs_next = h[(size_t)src_s[e + 1] * HID + d];
        const unsigned long long* eav =
            reinterpret_cast<const unsigned long long*>(&ea_s[e][0]);
        unsigned long long acc = 0ull;
        #pragma unroll
        for (int t = 0; t < 16; t++)
            fma2(acc, eav[t], wcol2[t]);
        float2 s = upk(acc);
        float v = fmaxf(s.x + s.y + bd + hs, 0.f);
        atomicAdd(&agg[(size_t)dst_s[e] * HID + d], v);
        hs = hs_next;
    }
}

// ---------------- fused classifier: hidden + @cls_w2 -----------------------
// Block: 128 threads, 64 edges.
// Phase 1: hid_s[e][d] = relu(P[src][d]+Q[dst][d]+ea@w1c+b1)
// Phase 2: out[e][o] = hid_s[e] . w2t[o] + b2[o]    (4 edges x 3 outs / thread)
#define CLS_E 64
#define HPAD 132

__global__ __launch_bounds__(128)
void cls_fused_kernel(const float* __restrict__ P,
                      const float* __restrict__ Q,
                      const int* __restrict__ src,
                      const int* __restrict__ dst,
                      const float* __restrict__ ea,
                      const float* __restrict__ w1c,  // [32,128]
                      const float* __restrict__ b1,   // [128]
                      const float* __restrict__ w2,   // [128,24]
                      const float* __restrict__ b2,   // [24]
                      float* __restrict__ out,        // [E,24]
                      int E)
{
    __shared__ float hid_s[CLS_E][HPAD];
    __shared__ float w2t[OUT][HPAD];
    __shared__ float ea_s[CLS_E][32];
    __shared__ int src_s[CLS_E];
    __shared__ int dst_s[CLS_E];

    const int tid = threadIdx.x;
    const int base = blockIdx.x * CLS_E;
    const int ne = min(CLS_E, E - base);
    if (ne <= 0) return;

    // load + transpose w2 (coalesced gmem reads, scattered STS)
    for (int idx = tid; idx < HID * OUT; idx += 128) {
        float v = w2[idx];
        w2t[idx % OUT][idx / OUT] = v;
    }
    for (int idx = tid; idx < ne * 32; idx += 128)
        ea_s[idx >> 5][idx & 31] = ea[(size_t)base * 32 + idx];
    if (tid < ne) {
        src_s[tid] = src[base + tid];
        dst_s[tid] = dst[base + tid];
    }
    __syncthreads();

    // ---- phase 1: hidden ----
    {
        const int d = tid;
        unsigned long long wcol2[16];
        #pragma unroll
        for (int t = 0; t < 16; t++)
            wcol2[t] = pk2(w1c[(2 * t) * HID + d], w1c[(2 * t + 1) * HID + d]);
        const float bd = b1[d];

        float pq = P[(size_t)src_s[0] * HID + d] + Q[(size_t)dst_s[0] * HID + d];
        for (int e = 0; e < ne; e++) {
            float pq_next = 0.f;
            if (e + 1 < ne)
                pq_next = P[(size_t)src_s[e + 1] * HID + d] +
                          Q[(size_t)dst_s[e + 1] * HID + d];
            const unsigned long long* eav =
                reinterpret_cast<const unsigned long long*>(&ea_s[e][0]);
            unsigned long long acc = 0ull;
            #pragma unroll
            for (int t = 0; t < 16; t++)
                fma2(acc, eav[t], wcol2[t]);
            float2 s = upk(acc);
            hid_s[e][d] = fmaxf(s.x + s.y + bd + pq, 0.f);
            pq = pq_next;
        }
    }
    __syncthreads();

    // ---- phase 2: [64 x 24] = hid_s[64 x 128] @ w2t^T ----
    const int oq = tid & 7;    // 8 groups of 3 outs
    const int eq = tid >> 3;   // 16 groups of 4 edges
    const int o0 = oq * 3;
    const int e0 = eq * 4;

    unsigned long long acc2[4][3];
    #pragma unroll
    for (int i = 0; i < 4; i++)
        #pragma unroll
        for (int j = 0; j < 3; j++) acc2[i][j] = 0ull;

    #pragma unroll 4
    for (int dch = 0; dch < HID; dch += 4) {
        unsigned long long h2[4][2], w2r[3][2];
        #pragma unroll
        for (int i = 0; i < 4; i++) {
            const unsigned long long* hp =
                reinterpret_cast<const unsigned long long*>(&hid_s[e0 + i][dch]);
            h2[i][0] = hp[0]; h2[i][1] = hp[1];
        }
        #pragma unroll
        for (int j = 0; j < 3; j++) {
            const unsigned long long* wp =
                reinterpret_cast<const unsigned long long*>(&w2t[o0 + j][dch]);
            w2r[j][0] = wp[0]; w2r[j][1] = wp[1];
        }
        #pragma unroll
        for (int i = 0; i < 4; i++)
            #pragma unroll
            for (int j = 0; j < 3; j++) {
                fma2(acc2[i][j], h2[i][0], w2r[j][0]);
                fma2(acc2[i][j], h2[i][1], w2r[j][1]);
            }
    }

    #pragma unroll
    for (int i = 0; i < 4; i++) {
        int e = e0 + i;
        if (e >= ne) continue;
        #pragma unroll
        for (int j = 0; j < 3; j++) {
            float2 s = upk(acc2[i][j]);
            out[(size_t)(base + e) * OUT + o0 + j] = s.x + s.y + b2[o0 + j];
        }
    }
}

// ---------------- host ----------------
extern "C" void kernel_launch(void* const* d_in, const int* in_sizes, int n_in,
                              void* d_out, int out_size)
{
    const float* x      = (const float*)d_in[0];
    const int*   eidx   = (const int*)  d_in[1];
    const float* ea     = (const float*)d_in[2];
    const float* lin1_w = (const float*)d_in[3];
    const float* lin1_b = (const float*)d_in[4];
    const float* cls_w1 = (const float*)d_in[23];
    const float* cls_b1 = (const float*)d_in[24];
    const float* cls_w2 = (const float*)d_in[25];
    const float* cls_b2 = (const float*)d_in[26];

    const int NN = in_sizes[0] / 64;
    const int E  = in_sizes[2] / 32;
    const int* src = eidx;
    const int* dst = eidx + E;

    float *h, *agg, *hid;
    cudaGetSymbolAddress((void**)&h,   g_h);
    cudaGetSymbolAddress((void**)&agg, g_agg);
    cudaGetSymbolAddress((void**)&hid, g_hid);

    const dim3 gnode(1, (unsigned)((NN + BM - 1) / BM));
    const int sblocks = (E + 31) / 32;
    const int cblocks = (E + CLS_E - 1) / CLS_E;
    const int copy_n4 = (NN * HID) / 4;
    const int copy_blocks = (copy_n4 + 255) / 256;

    sgemm_kernel<false><<<gnode, 256>>>(x, 64, lin1_w, HID, lin1_b, h, HID, NN, 64);

    for (int c = 0; c < 3; c++) {
        const float* ew = (const float*)d_in[5 + 6 * c];
        const float* eb = (const float*)d_in[6 + 6 * c];
        const float* w1 = (const float*)d_in[7 + 6 * c];
        const float* b1 = (const float*)d_in[8 + 6 * c];
        const float* w2 = (const float*)d_in[9 + 6 * c];
        const float* b2 = (const float*)d_in[10 + 6 * c];

        copy_kernel<<<copy_blocks, 256>>>(agg, h, copy_n4);
        edge_scatter_kernel<<<sblocks, 128>>>(h, src, dst, ea, ew, eb, agg, E);
        sgemm_kernel<true><<<gnode, 256>>>(agg, HID, w1, HID, b1, hid, HID, NN, HID);
        sgemm_kernel<true><<<gnode, 256>>>(hid, HID, w2, HID, b2, h, HID, NN, HID);
    }

    // P = h @ W1[0:128], Q = h @ W1[128:256]
    sgemm_kernel<false><<<gnode, 256>>>(h, HID, cls_w1, HID, nullptr, hid, HID, NN, HID);
    sgemm_kernel<false><<<gnode, 256>>>(h, HID, cls_w1 + 128 * HID, HID, nullptr, agg, HID, NN, HID);

    cls_fused_kernel<<<cblocks, 128>>>(hid, agg, src, dst, ea,
                                       cls_w1 + 256 * HID, cls_b1,
                                       cls_w2, cls_b2, (float*)d_out, E);
}